// round 4
// baseline (speedup 1.0000x reference)
#include <cuda_runtime.h>
#include <math.h>

// ChildSumTreeLSTM on a perfect binary tree.
// B=8, L=16384 leaves, N=2L-1=32767 nodes (heap order: children of j are 2j+1, 2j+2),
// D_IN = D_H = 256.
//
// Strategy:
//   - h, c stored per (batch, node) in __device__ globals (scratch; no allocation).
//   - Leaf level: fused GEMM [rows,256]@[256,768] + activation -> h, c.
//   - Per internal level n (14 levels):
//       fgate_kernel: s = sig(x@Wf + bf + h0@Uf)*c0 + sig(x@Wf + bf + h1@Uf)*c1
//       iou_kernel:   [x | h_sum] @ [Wiou; Uiou] (K=512, 3 col planes i/o/u)
//                     -> c = sig(i)*tanh(u) + s ; h = sig(o)*tanh(c)
//   - All GEMMs use mma.sync.m16n8k8 tf32 with a 3-term hi/lo split for ~fp32 accuracy.
//
// Tiling: CTA = 256 threads (8 warps as 2x4), CTA tile M=32 rows x 64 cols, K-chunk 16.
// hi/lo packed as float2 in smem so each fragment element is one LDS.64.

#define BB 8
#define LL 16384
#define NN 32767

__device__ float g_h[(size_t)BB * NN * 256];   // hidden state per (b, node)
__device__ float g_c[(size_t)BB * NN * 256];   // cell state per (b, node)
__device__ float g_s[(size_t)BB * (LL / 2) * 256]; // per-level forget-sum scratch

__device__ __forceinline__ float sigf(float v) {
    return 1.0f / (1.0f + expf(-v));
}

// Split a fp32 value into tf32 hi + tf32 lo (residual). hi has the top ~11
// mantissa bits; lo captures the next ~11. a*b ~= ah*bh + ah*bl + al*bh.
__device__ __forceinline__ float2 split_tf32(float v) {
    unsigned hu, lu;
    asm("cvt.rna.tf32.f32 %0, %1;" : "=r"(hu) : "f"(v));
    float hi = __uint_as_float(hu);
    float lo = v - hi;
    asm("cvt.rna.tf32.f32 %0, %1;" : "=r"(lu) : "f"(lo));
    return make_float2(hi, __uint_as_float(lu));
}

__device__ __forceinline__ void mma_tf32(float* d,
    unsigned a0, unsigned a1, unsigned a2, unsigned a3,
    unsigned b0, unsigned b1)
{
    asm volatile(
        "mma.sync.aligned.m16n8k8.row.col.f32.tf32.tf32.f32 "
        "{%0,%1,%2,%3}, {%4,%5,%6,%7}, {%8,%9}, {%0,%1,%2,%3};"
        : "+f"(d[0]), "+f"(d[1]), "+f"(d[2]), "+f"(d[3])
        : "r"(a0), "r"(a1), "r"(a2), "r"(a3), "r"(b0), "r"(b1));
}

// ---------------------------------------------------------------------------
// iou kernel: for rows (b, j) at level with n nodes (leaf: n = LL):
//   A = [ x_row (K 0..255) | h_sum (K 256..511, internal only) ]
//   B planes p=0,1,2: columns [p*256 + colbase, +64) of [Wiou; Uiou]
//   epilogue: c = sig(i)*tanh(u) + s ; h = sig(o)*tanh(c) ; write g_h, g_c.
// ---------------------------------------------------------------------------
__global__ __launch_bounds__(256) void iou_kernel(
    const float* __restrict__ x, const float* __restrict__ Wiou,
    const float* __restrict__ biou, const float* __restrict__ Uiou,
    int n, int lg, int leaf)
{
    __shared__ float2 As[32 * 20];        // [row][k] hi/lo, stride 20 (pad)
    __shared__ float2 Bs[3 * 16 * 72];    // [plane][k][col] hi/lo, stride 72 (pad)

    const int tid = threadIdx.x;
    const int rows = BB * n;
    const int K = leaf ? 256 : 512;
    const int colbase = blockIdx.y * 64;
    const int row0 = blockIdx.x * 32;
    const int nodebase = leaf ? (LL - 1) : (n - 1);

    const int lane = tid & 31, wid = tid >> 5;
    const int wm = wid >> 2, wn = wid & 3;
    const int g = lane >> 2, tg = lane & 3;

    float acc[3][2][4];
#pragma unroll
    for (int p = 0; p < 3; p++)
#pragma unroll
        for (int t = 0; t < 2; t++)
#pragma unroll
            for (int q = 0; q < 4; q++) acc[p][t][q] = 0.0f;

    for (int kc = 0; kc < K; kc += 16) {
        __syncthreads();
        // ---- load A chunk: 32 rows x 16 k ----
#pragma unroll
        for (int i = tid; i < 512; i += 256) {
            int r = i >> 4, kk = i & 15;
            int rowg = row0 + r;
            float v = 0.0f;
            if (rowg < rows) {
                int b = rowg >> lg;
                int j = rowg & (n - 1);
                int node = nodebase + j;
                int kg = kc + kk;
                if (kg < 256) {
                    v = x[((size_t)b * NN + node) * 256 + kg];
                } else {
                    size_t cb = ((size_t)b * NN + 2 * node + 1) * 256 + (kg - 256);
                    v = g_h[cb] + g_h[cb + 256];   // h_sum of the two children
                }
            }
            As[r * 20 + kk] = split_tf32(v);
        }
        // ---- load B chunk: 3 planes x 16 k x 64 cols ----
#pragma unroll
        for (int i = tid; i < 3072; i += 256) {
            int p = i >> 10, rem = i & 1023;
            int kk = rem >> 6, c = rem & 63;
            int kg = kc + kk;
            int gc = colbase + p * 256 + c;
            float v = (kg < 256) ? Wiou[(size_t)kg * 768 + gc]
                                 : Uiou[(size_t)(kg - 256) * 768 + gc];
            Bs[p * 1152 + kk * 72 + c] = split_tf32(v);
        }
        __syncthreads();
        // ---- MMA: 2 k-steps of 8 ----
#pragma unroll
        for (int ks = 0; ks < 2; ks++) {
            int ka = ks * 8;
            float2 fa0 = As[(wm * 16 + g    ) * 20 + ka + tg];
            float2 fa1 = As[(wm * 16 + g + 8) * 20 + ka + tg];
            float2 fa2 = As[(wm * 16 + g    ) * 20 + ka + tg + 4];
            float2 fa3 = As[(wm * 16 + g + 8) * 20 + ka + tg + 4];
            unsigned ah0 = __float_as_uint(fa0.x), al0 = __float_as_uint(fa0.y);
            unsigned ah1 = __float_as_uint(fa1.x), al1 = __float_as_uint(fa1.y);
            unsigned ah2 = __float_as_uint(fa2.x), al2 = __float_as_uint(fa2.y);
            unsigned ah3 = __float_as_uint(fa3.x), al3 = __float_as_uint(fa3.y);
#pragma unroll
            for (int p = 0; p < 3; p++) {
#pragma unroll
                for (int t = 0; t < 2; t++) {
                    int cb2 = wn * 16 + t * 8 + g;
                    float2 fb0 = Bs[p * 1152 + (ka + tg    ) * 72 + cb2];
                    float2 fb1 = Bs[p * 1152 + (ka + tg + 4) * 72 + cb2];
                    unsigned bh0 = __float_as_uint(fb0.x), bl0 = __float_as_uint(fb0.y);
                    unsigned bh1 = __float_as_uint(fb1.x), bl1 = __float_as_uint(fb1.y);
                    mma_tf32(acc[p][t], ah0, ah1, ah2, ah3, bh0, bh1);
                    mma_tf32(acc[p][t], ah0, ah1, ah2, ah3, bl0, bl1);
                    mma_tf32(acc[p][t], al0, al1, al2, al3, bh0, bh1);
                }
            }
        }
    }

    // ---- epilogue: activations + write h, c ----
#pragma unroll
    for (int t = 0; t < 2; t++) {
#pragma unroll
        for (int half = 0; half < 2; half++) {
            int r = wm * 16 + g + half * 8;
            int rowg = row0 + r;
            if (rowg >= rows) continue;
            int cl = wn * 16 + t * 8 + tg * 2;
            int gc = colbase + cl;
            int b = rowg >> lg;
            int j = rowg & (n - 1);
            int node = nodebase + j;
            float hv[2], cv[2];
#pragma unroll
            for (int q = 0; q < 2; q++) {
                float iv = acc[0][t][half * 2 + q] + biou[gc + q];
                float ov = acc[1][t][half * 2 + q] + biou[gc + q + 256];
                float uv = acc[2][t][half * 2 + q] + biou[gc + q + 512];
                float sv = leaf ? 0.0f : g_s[(size_t)rowg * 256 + gc + q];
                float cn = sigf(iv) * tanhf(uv) + sv;
                cv[q] = cn;
                hv[q] = sigf(ov) * tanhf(cn);
            }
            size_t idx = ((size_t)b * NN + node) * 256 + gc;
            *(float2*)(&g_h[idx]) = make_float2(hv[0], hv[1]);
            *(float2*)(&g_c[idx]) = make_float2(cv[0], cv[1]);
        }
    }
}

// ---------------------------------------------------------------------------
// fgate kernel: per parent row, compute
//   s = sig(x@Wf + bf + h_c0@Uf)*c0 + sig(x@Wf + bf + h_c1@Uf)*c1
// Stage 1: accf[32 x 64]  = x_parent @ Wf        (K=256)
// Stage 2: accp[64 x 64]  = h_child  @ Uf        (child rows interleaved 2/parent)
// Epilogue combines via smem staging, writes g_s.
// ---------------------------------------------------------------------------
__global__ __launch_bounds__(256) void fgate_kernel(
    const float* __restrict__ x, const float* __restrict__ Wf,
    const float* __restrict__ bf, const float* __restrict__ Uf,
    int n, int lg)
{
    __shared__ float2 As[64 * 20];
    __shared__ float2 Bs[16 * 72];
    __shared__ float stage[6144];   // [0,2048): accf ; [2048,6144): accp

    const int tid = threadIdx.x;
    const int rows = BB * n;
    const int colbase = blockIdx.y * 64;
    const int row0 = blockIdx.x * 32;

    const int lane = tid & 31, wid = tid >> 5;
    const int wm = wid >> 2, wn = wid & 3;
    const int g = lane >> 2, tg = lane & 3;

    float accf[2][4];
    float accp[2][2][4];
#pragma unroll
    for (int t = 0; t < 2; t++)
#pragma unroll
        for (int q = 0; q < 4; q++) accf[t][q] = 0.0f;
#pragma unroll
    for (int s = 0; s < 2; s++)
#pragma unroll
        for (int t = 0; t < 2; t++)
#pragma unroll
            for (int q = 0; q < 4; q++) accp[s][t][q] = 0.0f;

    // ---- stage 1: x_parent @ Wf ----
    for (int kc = 0; kc < 256; kc += 16) {
        __syncthreads();
#pragma unroll
        for (int i = tid; i < 512; i += 256) {
            int r = i >> 4, kk = i & 15;
            int rowg = row0 + r;
            float v = 0.0f;
            if (rowg < rows) {
                int b = rowg >> lg, j = rowg & (n - 1);
                int node = n - 1 + j;
                v = x[((size_t)b * NN + node) * 256 + kc + kk];
            }
            As[r * 20 + kk] = split_tf32(v);
        }
#pragma unroll
        for (int i = tid; i < 1024; i += 256) {
            int kk = i >> 6, c = i & 63;
            float v = Wf[(size_t)(kc + kk) * 256 + colbase + c];
            Bs[kk * 72 + c] = split_tf32(v);
        }
        __syncthreads();
#pragma unroll
        for (int ks = 0; ks < 2; ks++) {
            int ka = ks * 8;
            float2 fa0 = As[(wm * 16 + g    ) * 20 + ka + tg];
            float2 fa1 = As[(wm * 16 + g + 8) * 20 + ka + tg];
            float2 fa2 = As[(wm * 16 + g    ) * 20 + ka + tg + 4];
            float2 fa3 = As[(wm * 16 + g + 8) * 20 + ka + tg + 4];
            unsigned ah0 = __float_as_uint(fa0.x), al0 = __float_as_uint(fa0.y);
            unsigned ah1 = __float_as_uint(fa1.x), al1 = __float_as_uint(fa1.y);
            unsigned ah2 = __float_as_uint(fa2.x), al2 = __float_as_uint(fa2.y);
            unsigned ah3 = __float_as_uint(fa3.x), al3 = __float_as_uint(fa3.y);
#pragma unroll
            for (int t = 0; t < 2; t++) {
                int cb2 = wn * 16 + t * 8 + g;
                float2 fb0 = Bs[(ka + tg    ) * 72 + cb2];
                float2 fb1 = Bs[(ka + tg + 4) * 72 + cb2];
                unsigned bh0 = __float_as_uint(fb0.x), bl0 = __float_as_uint(fb0.y);
                unsigned bh1 = __float_as_uint(fb1.x), bl1 = __float_as_uint(fb1.y);
                mma_tf32(accf[t], ah0, ah1, ah2, ah3, bh0, bh1);
                mma_tf32(accf[t], ah0, ah1, ah2, ah3, bl0, bl1);
                mma_tf32(accf[t], al0, al1, al2, al3, bh0, bh1);
            }
        }
    }

    // ---- stage 2: h_child @ Uf (64 child rows: 2 per parent, interleaved) ----
    for (int kc = 0; kc < 256; kc += 16) {
        __syncthreads();
#pragma unroll
        for (int i = tid; i < 1024; i += 256) {
            int rr = i >> 4, kk = i & 15;
            int pr = row0 + (rr >> 1), sel = rr & 1;
            float v = 0.0f;
            if (pr < rows) {
                int b = pr >> lg, j = pr & (n - 1);
                int child = 2 * n - 1 + 2 * j + sel;
                v = g_h[((size_t)b * NN + child) * 256 + kc + kk];
            }
            As[rr * 20 + kk] = split_tf32(v);
        }
#pragma unroll
        for (int i = tid; i < 1024; i += 256) {
            int kk = i >> 6, c = i & 63;
            float v = Uf[(size_t)(kc + kk) * 256 + colbase + c];
            Bs[kk * 72 + c] = split_tf32(v);
        }
        __syncthreads();
#pragma unroll
        for (int ks = 0; ks < 2; ks++) {
            int ka = ks * 8;
#pragma unroll
            for (int s = 0; s < 2; s++) {
                int ar = wm * 32 + s * 16 + g;
                float2 fa0 = As[(ar    ) * 20 + ka + tg];
                float2 fa1 = As[(ar + 8) * 20 + ka + tg];
                float2 fa2 = As[(ar    ) * 20 + ka + tg + 4];
                float2 fa3 = As[(ar + 8) * 20 + ka + tg + 4];
                unsigned ah0 = __float_as_uint(fa0.x), al0 = __float_as_uint(fa0.y);
                unsigned ah1 = __float_as_uint(fa1.x), al1 = __float_as_uint(fa1.y);
                unsigned ah2 = __float_as_uint(fa2.x), al2 = __float_as_uint(fa2.y);
                unsigned ah3 = __float_as_uint(fa3.x), al3 = __float_as_uint(fa3.y);
#pragma unroll
                for (int t = 0; t < 2; t++) {
                    int cb2 = wn * 16 + t * 8 + g;
                    float2 fb0 = Bs[(ka + tg    ) * 72 + cb2];
                    float2 fb1 = Bs[(ka + tg + 4) * 72 + cb2];
                    unsigned bh0 = __float_as_uint(fb0.x), bl0 = __float_as_uint(fb0.y);
                    unsigned bh1 = __float_as_uint(fb1.x), bl1 = __float_as_uint(fb1.y);
                    mma_tf32(accp[s][t], ah0, ah1, ah2, ah3, bh0, bh1);
                    mma_tf32(accp[s][t], ah0, ah1, ah2, ah3, bl0, bl1);
                    mma_tf32(accp[s][t], al0, al1, al2, al3, bh0, bh1);
                }
            }
        }
    }

    // ---- stage accf/accp through smem, combine, write s ----
#pragma unroll
    for (int t = 0; t < 2; t++)
#pragma unroll
        for (int half = 0; half < 2; half++)
#pragma unroll
            for (int q = 0; q < 2; q++) {
                int r = wm * 16 + g + half * 8;
                int c = wn * 16 + t * 8 + tg * 2 + q;
                stage[r * 64 + c] = accf[t][half * 2 + q];
            }
#pragma unroll
    for (int s = 0; s < 2; s++)
#pragma unroll
        for (int t = 0; t < 2; t++)
#pragma unroll
            for (int half = 0; half < 2; half++)
#pragma unroll
                for (int q = 0; q < 2; q++) {
                    int rr = wm * 32 + s * 16 + g + half * 8;
                    int c = wn * 16 + t * 8 + tg * 2 + q;
                    stage[2048 + rr * 64 + c] = accp[s][t][half * 2 + q];
                }
    __syncthreads();

    for (int i = tid; i < 2048; i += 256) {
        int r = i >> 6, cl = i & 63;
        int rowg = row0 + r;
        if (rowg >= rows) continue;
        int gc = colbase + cl;
        int b = rowg >> lg, j = rowg & (n - 1);
        int ch0 = 2 * n - 1 + 2 * j;
        float fpre = stage[i] + bf[gc];
        float p0 = stage[2048 + (2 * r    ) * 64 + cl];
        float p1 = stage[2048 + (2 * r + 1) * 64 + cl];
        float c0 = g_c[((size_t)b * NN + ch0    ) * 256 + gc];
        float c1 = g_c[((size_t)b * NN + ch0 + 1) * 256 + gc];
        float sv = sigf(fpre + p0) * c0 + sigf(fpre + p1) * c1;
        g_s[(size_t)rowg * 256 + gc] = sv;
    }
}

// Final gather: out[b] = concat(h_root, c_root)
__global__ void out_kernel(float* __restrict__ out) {
    int i = blockIdx.x * blockDim.x + threadIdx.x;
    if (i >= BB * 512) return;
    int b = i >> 9, r = i & 511;
    size_t base = (size_t)b * NN * 256;
    out[i] = (r < 256) ? g_h[base + r] : g_c[base + r - 256];
}

extern "C" void kernel_launch(void* const* d_in, const int* in_sizes, int n_in,
                              void* d_out, int out_size)
{
    (void)in_sizes; (void)n_in; (void)out_size;
    const float* x    = (const float*)d_in[0];
    const float* Wiou = (const float*)d_in[1];
    const float* biou = (const float*)d_in[2];
    const float* Uiou = (const float*)d_in[3];
    const float* Wf   = (const float*)d_in[4];
    const float* bf   = (const float*)d_in[5];
    const float* Uf   = (const float*)d_in[6];

    // Leaf level: rows = B*L, K=256, nodes L-1 .. 2L-2
    {
        int rows = BB * LL;
        dim3 grid((rows + 31) / 32, 4);
        iou_kernel<<<grid, 256>>>(x, Wiou, biou, Uiou, LL, 14, 1);
    }
    // Internal levels: n = 8192 .. 1
    int lg = 13;
    for (int n = LL / 2; n >= 1; n >>= 1, lg--) {
        int rows = BB * n;
        dim3 grid((rows + 31) / 32, 4);
        fgate_kernel<<<grid, 256>>>(x, Wf, bf, Uf, n, lg);
        iou_kernel<<<grid, 256>>>(x, Wiou, biou, Uiou, n, lg, 0);
    }
    out_kernel<<<16, 256>>>((float*)d_out);
}

// round 8
// speedup vs baseline: 2.3604x; 2.3604x over previous
#include <cuda_runtime.h>
#include <math.h>

// ChildSumTreeLSTM, perfect binary tree. B=8, L=16384, N=32767, D=H=256.
// Per level: fgate (s = sig(xWf+bf+h0 Uf)*c0 + sig(..h1..)*c1), then
// iou ([x|h_sum]@[Wiou;Uiou], 3 col planes) with in-register activation epilogue.
// GEMM core: mma.sync.m16n8k8 tf32 with 3-term hi/lo split (~fp32 accuracy).
// CTA = 256 thr (8 warps, 2x4). CTA tile M=64 x N=64(/plane). K-chunk 16.
// Weights pre-split to float2(hi,lo) once per launch; A split in the loader.
// Register-prefetch pipeline: next chunk's global loads overlap current MMAs.

#define BB 8
#define LL 16384
#define NN 32767

__device__ float g_h[(size_t)BB * NN * 256];
__device__ float g_c[(size_t)BB * NN * 256];
__device__ float g_s[(size_t)BB * (LL / 2) * 256];
__device__ float2 g_WU2[512 * 768];   // [Wiou;Uiou] pre-split
__device__ float2 g_Wf2[256 * 256];
__device__ float2 g_Uf2[256 * 256];

__device__ __forceinline__ float sigf(float v) {
    return 1.0f / (1.0f + __expf(-v));
}
__device__ __forceinline__ float tanhfast(float v) {
    return 2.0f * sigf(2.0f * v) - 1.0f;   // saturation-safe
}

__device__ __forceinline__ float2 split_tf32(float v) {
    unsigned hu, lu;
    asm("cvt.rna.tf32.f32 %0, %1;" : "=r"(hu) : "f"(v));
    float hi = __uint_as_float(hu);
    float lo = v - hi;
    asm("cvt.rna.tf32.f32 %0, %1;" : "=r"(lu) : "f"(lo));
    return make_float2(hi, __uint_as_float(lu));
}

__device__ __forceinline__ void mma_tf32(float* d,
    unsigned a0, unsigned a1, unsigned a2, unsigned a3,
    unsigned b0, unsigned b1)
{
    asm volatile(
        "mma.sync.aligned.m16n8k8.row.col.f32.tf32.tf32.f32 "
        "{%0,%1,%2,%3}, {%4,%5,%6,%7}, {%8,%9}, {%0,%1,%2,%3};"
        : "+f"(d[0]), "+f"(d[1]), "+f"(d[2]), "+f"(d[3])
        : "r"(a0), "r"(a1), "r"(a2), "r"(a3), "r"(b0), "r"(b1));
}

// triple split-MMA: ah*bh + ah*bl + al*bh
__device__ __forceinline__ void mma3(float* d, const float2 fa[4],
                                     float2 fb0, float2 fb1)
{
    unsigned ah0 = __float_as_uint(fa[0].x), al0 = __float_as_uint(fa[0].y);
    unsigned ah1 = __float_as_uint(fa[1].x), al1 = __float_as_uint(fa[1].y);
    unsigned ah2 = __float_as_uint(fa[2].x), al2 = __float_as_uint(fa[2].y);
    unsigned ah3 = __float_as_uint(fa[3].x), al3 = __float_as_uint(fa[3].y);
    unsigned bh0 = __float_as_uint(fb0.x),  bl0 = __float_as_uint(fb0.y);
    unsigned bh1 = __float_as_uint(fb1.x),  bl1 = __float_as_uint(fb1.y);
    mma_tf32(d, ah0, ah1, ah2, ah3, bh0, bh1);
    mma_tf32(d, ah0, ah1, ah2, ah3, bl0, bl1);
    mma_tf32(d, al0, al1, al2, al3, bh0, bh1);
}

// ---------------------------------------------------------------------------
// prep: pre-split weights into hi/lo float2
// ---------------------------------------------------------------------------
__global__ void prep_kernel(const float* __restrict__ Wiou,
                            const float* __restrict__ Uiou,
                            const float* __restrict__ Wf,
                            const float* __restrict__ Uf)
{
    int i = blockIdx.x * blockDim.x + threadIdx.x;
    if (i < 512 * 768) {
        int k = i / 768, c = i - k * 768;
        float v = (k < 256) ? Wiou[k * 768 + c] : Uiou[(k - 256) * 768 + c];
        g_WU2[i] = split_tf32(v);
    }
    int j = i - 512 * 768;
    if (j >= 0 && j < 65536) g_Wf2[j] = split_tf32(Wf[j]);
    int l = j - 65536;
    if (l >= 0 && l < 65536) g_Uf2[l] = split_tf32(Uf[l]);
}

// ---------------------------------------------------------------------------
// iou kernel. CTA tile: 64 rows x (3 planes x 64 cols). K = 256 (leaf) / 512.
// ---------------------------------------------------------------------------
__global__ __launch_bounds__(256, 2) void iou_kernel(
    const float* __restrict__ x, const float* __restrict__ biou,
    int n, int lg, int leaf)
{
    __shared__ __align__(16) float2 As[64 * 20];       // [row][k] stride 20
    __shared__ __align__(16) float2 Bs[3 * 16 * 68];   // [p][k][c] stride 68

    const int tid = threadIdx.x;
    const int rows = BB * n;
    const int K = leaf ? 256 : 512;
    const int colbase = blockIdx.y * 64;
    const int row0 = blockIdx.x * 64;
    const int nodebase = leaf ? (LL - 1) : (n - 1);

    const int lane = tid & 31, wid = tid >> 5;
    const int wm = wid >> 2, wn = wid & 3;
    const int g = lane >> 2, tg = lane & 3;

    // ---- loader thread mapping (folded address algebra) ----
    const int ar  = tid >> 2;                 // A row 0..63
    const int akq = (tid & 3) << 2;           // A k offset 0/4/8/12
    const int arow = row0 + ar;
    const bool aval = arow < rows;
    const int ab = arow >> lg, aj = arow & (n - 1);
    const int anode = nodebase + aj;
    // child node index; clamp for the leaf pass (never dereferenced there,
    // but keep every formed address in-bounds)
    const int cnode = leaf ? 0 : (2 * anode + 1);
    const float* xp = x + ((size_t)ab * NN + anode) * 256 + akq;
    const float* hp = g_h + ((size_t)ab * NN + cnode) * 256 + akq;
    float2* asdst = &As[ar * 20 + akq];

    const int t6 = tid >> 6;                  // 0..3
    const int bc = tid & 63;
    const int bsm0 = t6 * 68 + bc;            // Bs: + (jj&3)*4*68 + (jj>>2)*1088
    const int bgl0 = t6 * 768 + colbase + bc; // g_WU2: + (jj&3)*4*768 + (jj>>2)*256

    float acc[3][2][2][4];                    // [plane][mt][nt][e]
#pragma unroll
    for (int p = 0; p < 3; p++)
#pragma unroll
        for (int mt = 0; mt < 2; mt++)
#pragma unroll
            for (int nt = 0; nt < 2; nt++)
#pragma unroll
                for (int e = 0; e < 4; e++) acc[p][mt][nt][e] = 0.0f;

    float4 apref = make_float4(0.f, 0.f, 0.f, 0.f);
    float2 bpref[12];

    // prologue: load chunk 0
    if (aval) apref = *(const float4*)xp;
#pragma unroll
    for (int jj = 0; jj < 12; jj++)
        bpref[jj] = g_WU2[(size_t)((jj & 3) * 4) * 768 + (jj >> 2) * 256 + bgl0];

    for (int kc = 0; kc < K; kc += 16) {
        __syncthreads();
        // store prefetched chunk to smem
        {
            float2 s0 = split_tf32(apref.x), s1 = split_tf32(apref.y);
            float2 s2 = split_tf32(apref.z), s3 = split_tf32(apref.w);
            float4* p4 = (float4*)asdst;
            p4[0] = make_float4(s0.x, s0.y, s1.x, s1.y);
            p4[1] = make_float4(s2.x, s2.y, s3.x, s3.y);
        }
#pragma unroll
        for (int jj = 0; jj < 12; jj++)
            Bs[(jj >> 2) * 1088 + (jj & 3) * (4 * 68) + bsm0] = bpref[jj];
        __syncthreads();

        // prefetch next chunk
        int kn = kc + 16;
        if (kn < K) {
            if (aval) {
                if (kn < 256) {
                    apref = *(const float4*)(xp + kn);
                } else {
                    float4 h0 = *(const float4*)(hp + (kn - 256));
                    float4 h1 = *(const float4*)(hp + (kn - 256) + 256);
                    apref = make_float4(h0.x + h1.x, h0.y + h1.y,
                                        h0.z + h1.z, h0.w + h1.w);
                }
            }
            size_t gb = (size_t)kn * 768;
#pragma unroll
            for (int jj = 0; jj < 12; jj++)
                bpref[jj] = g_WU2[gb + (size_t)((jj & 3) * 4) * 768 +
                                  (jj >> 2) * 256 + bgl0];
        }

        // compute 2 k-steps
#pragma unroll
        for (int ks = 0; ks < 2; ks++) {
            int ka = ks * 8;
            float2 fa[2][4];
#pragma unroll
            for (int mt = 0; mt < 2; mt++) {
                const float2* ap = &As[(wm * 32 + mt * 16 + g) * 20 + ka + tg];
                fa[mt][0] = ap[0];
                fa[mt][1] = ap[8 * 20];
                fa[mt][2] = ap[4];
                fa[mt][3] = ap[8 * 20 + 4];
            }
#pragma unroll
            for (int p = 0; p < 3; p++) {
#pragma unroll
                for (int nt = 0; nt < 2; nt++) {
                    const float2* bp =
                        &Bs[p * 1088 + (ka + tg) * 68 + wn * 16 + nt * 8 + g];
                    float2 fb0 = bp[0];
                    float2 fb1 = bp[4 * 68];
#pragma unroll
                    for (int mt = 0; mt < 2; mt++)
                        mma3(acc[p][mt][nt], fa[mt], fb0, fb1);
                }
            }
        }
    }

    // ---- epilogue ----
#pragma unroll
    for (int mt = 0; mt < 2; mt++) {
#pragma unroll
        for (int rh = 0; rh < 2; rh++) {
            int r = wm * 32 + mt * 16 + rh * 8 + g;
            int rowg = row0 + r;
            if (rowg >= rows) continue;
            int b = rowg >> lg, j = rowg & (n - 1);
            size_t obase = ((size_t)b * NN + nodebase + j) * 256;
#pragma unroll
            for (int nt = 0; nt < 2; nt++) {
                int gc = colbase + wn * 16 + nt * 8 + tg * 2;
                float2 bi = *(const float2*)&biou[gc];
                float2 bo = *(const float2*)&biou[gc + 256];
                float2 bu = *(const float2*)&biou[gc + 512];
                float2 sv = leaf ? make_float2(0.f, 0.f)
                                 : *(const float2*)&g_s[(size_t)rowg * 256 + gc];
                float hv[2], cv[2];
#pragma unroll
                for (int q = 0; q < 2; q++) {
                    int e = rh * 2 + q;
                    float iv = acc[0][mt][nt][e] + (q ? bi.y : bi.x);
                    float ov = acc[1][mt][nt][e] + (q ? bo.y : bo.x);
                    float uv = acc[2][mt][nt][e] + (q ? bu.y : bu.x);
                    float cn = sigf(iv) * tanhfast(uv) + (q ? sv.y : sv.x);
                    cv[q] = cn;
                    hv[q] = sigf(ov) * tanhfast(cn);
                }
                *(float2*)&g_h[obase + gc] = make_float2(hv[0], hv[1]);
                *(float2*)&g_c[obase + gc] = make_float2(cv[0], cv[1]);
            }
        }
    }
}

// ---------------------------------------------------------------------------
// fgate kernel. CTA: 64 parent rows x 64 cols.
// Stage 1: accf = x_parent @ Wf (K=256).
// Stage 2: accp[sel] = h_child(sel) @ Uf, sel in {0,1}, SAME fragment layout
//          as stage 1 -> in-register combine, no smem staging.
// ---------------------------------------------------------------------------
__global__ __launch_bounds__(256, 2) void fgate_kernel(
    const float* __restrict__ x, const float* __restrict__ bf,
    int n, int lg)
{
    __shared__ __align__(16) float2 As[128 * 20];
    __shared__ __align__(16) float2 Bs[16 * 68];

    const int tid = threadIdx.x;
    const int rows = BB * n;
    const int colbase = blockIdx.y * 64;
    const int row0 = blockIdx.x * 64;

    const int lane = tid & 31, wid = tid >> 5;
    const int wm = wid >> 2, wn = wid & 3;
    const int g = lane >> 2, tg = lane & 3;

    const int ar  = tid >> 2;
    const int akq = (tid & 3) << 2;
    const int arow = row0 + ar;
    const bool aval = arow < rows;
    const int ab = arow >> lg, aj = arow & (n - 1);
    const int anode = n - 1 + aj;
    const float* xp = x + ((size_t)ab * NN + anode) * 256 + akq;
    const float* hp = g_h + ((size_t)ab * NN + (2 * anode + 1)) * 256 + akq;
    float2* asdst = &As[ar * 20 + akq];

    const int t6 = tid >> 6;
    const int bc = tid & 63;
    const int bsm0 = t6 * 68 + bc;
    const int bgl0 = t6 * 256 + colbase + bc;

    float accf[2][2][4];
    float accp[2][2][2][4];
#pragma unroll
    for (int mt = 0; mt < 2; mt++)
#pragma unroll
        for (int nt = 0; nt < 2; nt++)
#pragma unroll
            for (int e = 0; e < 4; e++) {
                accf[mt][nt][e] = 0.0f;
                accp[0][mt][nt][e] = 0.0f;
                accp[1][mt][nt][e] = 0.0f;
            }

    // ================= stage 1: x @ Wf =================
    {
        float4 apref = make_float4(0.f, 0.f, 0.f, 0.f);
        float2 bpref[4];
        if (aval) apref = *(const float4*)xp;
#pragma unroll
        for (int jj = 0; jj < 4; jj++)
            bpref[jj] = g_Wf2[(size_t)(jj * 4) * 256 + bgl0];

        for (int kc = 0; kc < 256; kc += 16) {
            __syncthreads();
            {
                float2 s0 = split_tf32(apref.x), s1 = split_tf32(apref.y);
                float2 s2 = split_tf32(apref.z), s3 = split_tf32(apref.w);
                float4* p4 = (float4*)asdst;
                p4[0] = make_float4(s0.x, s0.y, s1.x, s1.y);
                p4[1] = make_float4(s2.x, s2.y, s3.x, s3.y);
            }
#pragma unroll
            for (int jj = 0; jj < 4; jj++)
                Bs[jj * (4 * 68) + bsm0] = bpref[jj];
            __syncthreads();

            int kn = kc + 16;
            if (kn < 256) {
                if (aval) apref = *(const float4*)(xp + kn);
                size_t gb = (size_t)kn * 256;
#pragma unroll
                for (int jj = 0; jj < 4; jj++)
                    bpref[jj] = g_Wf2[gb + (size_t)(jj * 4) * 256 + bgl0];
            }

#pragma unroll
            for (int ks = 0; ks < 2; ks++) {
                int ka = ks * 8;
                float2 fb[2][2];
#pragma unroll
                for (int nt = 0; nt < 2; nt++) {
                    const float2* bp = &Bs[(ka + tg) * 68 + wn * 16 + nt * 8 + g];
                    fb[nt][0] = bp[0];
                    fb[nt][1] = bp[4 * 68];
                }
#pragma unroll
                for (int mt = 0; mt < 2; mt++) {
                    float2 fa[4];
                    const float2* ap = &As[(wm * 32 + mt * 16 + g) * 20 + ka + tg];
                    fa[0] = ap[0]; fa[1] = ap[8 * 20];
                    fa[2] = ap[4]; fa[3] = ap[8 * 20 + 4];
#pragma unroll
                    for (int nt = 0; nt < 2; nt++)
                        mma3(accf[mt][nt], fa, fb[nt][0], fb[nt][1]);
                }
            }
        }
    }

    // ================= stage 2: h_child @ Uf (both sels) =================
    {
        float4 apref0 = make_float4(0.f, 0.f, 0.f, 0.f);
        float4 apref1 = make_float4(0.f, 0.f, 0.f, 0.f);
        float2 bpref[4];
        if (aval) {
            apref0 = *(const float4*)hp;
            apref1 = *(const float4*)(hp + 256);
        }
#pragma unroll
        for (int jj = 0; jj < 4; jj++)
            bpref[jj] = g_Uf2[(size_t)(jj * 4) * 256 + bgl0];

        for (int kc = 0; kc < 256; kc += 16) {
            __syncthreads();
            {
                float2 s0 = split_tf32(apref0.x), s1 = split_tf32(apref0.y);
                float2 s2 = split_tf32(apref0.z), s3 = split_tf32(apref0.w);
                float4* p4 = (float4*)asdst;
                p4[0] = make_float4(s0.x, s0.y, s1.x, s1.y);
                p4[1] = make_float4(s2.x, s2.y, s3.x, s3.y);
                s0 = split_tf32(apref1.x); s1 = split_tf32(apref1.y);
                s2 = split_tf32(apref1.z); s3 = split_tf32(apref1.w);
                p4 = (float4*)(asdst + 64 * 20);
                p4[0] = make_float4(s0.x, s0.y, s1.x, s1.y);
                p4[1] = make_float4(s2.x, s2.y, s3.x, s3.y);
            }
#pragma unroll
            for (int jj = 0; jj < 4; jj++)
                Bs[jj * (4 * 68) + bsm0] = bpref[jj];
            __syncthreads();

            int kn = kc + 16;
            if (kn < 256) {
                if (aval) {
                    apref0 = *(const float4*)(hp + kn);
                    apref1 = *(const float4*)(hp + kn + 256);
                }
                size_t gb = (size_t)kn * 256;
#pragma unroll
                for (int jj = 0; jj < 4; jj++)
                    bpref[jj] = g_Uf2[gb + (size_t)(jj * 4) * 256 + bgl0];
            }

#pragma unroll
            for (int ks = 0; ks < 2; ks++) {
                int ka = ks * 8;
                float2 fb[2][2];
#pragma unroll
                for (int nt = 0; nt < 2; nt++) {
                    const float2* bp = &Bs[(ka + tg) * 68 + wn * 16 + nt * 8 + g];
                    fb[nt][0] = bp[0];
                    fb[nt][1] = bp[4 * 68];
                }
#pragma unroll
                for (int sel = 0; sel < 2; sel++) {
#pragma unroll
                    for (int mt = 0; mt < 2; mt++) {
                        float2 fa[4];
                        const float2* ap =
                            &As[(sel * 64 + wm * 32 + mt * 16 + g) * 20 + ka + tg];
                        fa[0] = ap[0]; fa[1] = ap[8 * 20];
                        fa[2] = ap[4]; fa[3] = ap[8 * 20 + 4];
#pragma unroll
                        for (int nt = 0; nt < 2; nt++)
                            mma3(accp[sel][mt][nt], fa, fb[nt][0], fb[nt][1]);
                    }
                }
            }
        }
    }

    // ================= epilogue: in-register combine =================
#pragma unroll
    for (int mt = 0; mt < 2; mt++) {
#pragma unroll
        for (int rh = 0; rh < 2; rh++) {
            int r = wm * 32 + mt * 16 + rh * 8 + g;
            int rowg = row0 + r;
            if (rowg >= rows) continue;
            int b = rowg >> lg, j = rowg & (n - 1);
            int node = n - 1 + j;
            size_t cb = ((size_t)b * NN + 2 * node + 1) * 256;
#pragma unroll
            for (int nt = 0; nt < 2; nt++) {
                int gc = colbase + wn * 16 + nt * 8 + tg * 2;
                float2 bfv = *(const float2*)&bf[gc];
                float2 c0 = *(const float2*)&g_c[cb + gc];
                float2 c1 = *(const float2*)&g_c[cb + 256 + gc];
                float s0, s1;
                {
                    int e = rh * 2;
                    float fpre = accf[mt][nt][e] + bfv.x;
                    s0 = sigf(fpre + accp[0][mt][nt][e]) * c0.x +
                         sigf(fpre + accp[1][mt][nt][e]) * c1.x;
                }
                {
                    int e = rh * 2 + 1;
                    float fpre = accf[mt][nt][e] + bfv.y;
                    s1 = sigf(fpre + accp[0][mt][nt][e]) * c0.y +
                         sigf(fpre + accp[1][mt][nt][e]) * c1.y;
                }
                *(float2*)&g_s[(size_t)rowg * 256 + gc] = make_float2(s0, s1);
            }
        }
    }
}

// Final gather: out[b] = concat(h_root, c_root)
__global__ void out_kernel(float* __restrict__ out) {
    int i = blockIdx.x * blockDim.x + threadIdx.x;
    if (i >= BB * 512) return;
    int b = i >> 9, r = i & 511;
    size_t base = (size_t)b * NN * 256;
    out[i] = (r < 256) ? g_h[base + r] : g_c[base + r - 256];
}

extern "C" void kernel_launch(void* const* d_in, const int* in_sizes, int n_in,
                              void* d_out, int out_size)
{
    (void)in_sizes; (void)n_in; (void)out_size;
    const float* x    = (const float*)d_in[0];
    const float* Wiou = (const float*)d_in[1];
    const float* biou = (const float*)d_in[2];
    const float* Uiou = (const float*)d_in[3];
    const float* Wf   = (const float*)d_in[4];
    const float* bf   = (const float*)d_in[5];
    const float* Uf   = (const float*)d_in[6];

    prep_kernel<<<2048, 256>>>(Wiou, Uiou, Wf, Uf);

    // Leaf level: rows = B*L = 131072
    iou_kernel<<<dim3(2048, 4), 256>>>(x, biou, LL, 14, 1);

    // Internal levels
    int lg = 13;
    for (int n = LL / 2; n >= 1; n >>= 1, lg--) {
        int rows = BB * n;
        int gx = (rows + 63) / 64;
        fgate_kernel<<<dim3(gx, 4), 256>>>(x, bf, n, lg);
        iou_kernel<<<dim3(gx, 4), 256>>>(x, biou, n, lg, 0);
    }
    out_kernel<<<16, 256>>>((float*)d_out);
}